// round 16
// baseline (speedup 1.0000x reference)
#include <cuda_runtime.h>
#include <cuda_bf16.h>
#include <cstdint>

// Problem constants
#define B_ 8
#define C_ 256
#define H_ 25
#define W_ 25
#define N_ 256
#define OUT_ 7
#define NBIN 49
#define IN_ 12544   // C*7*7
#define DFC_ 1024
#define FCC_ 512
#define SS_ (25.0f/255.0f)
#define TRANS_STD_ 0.1f

// fp32 scratch
__device__ float g_xt[B_*H_*W_*C_];
__device__ float g_p0[N_*IN_];
__device__ float g_h2[N_*DFC_];
__device__ float g_off[N_*2*NBIN];
__device__ float g_p1[N_*IN_];
__device__ float g_f2[N_*FCC_];
__device__ float g_part[4194304];      // split-K partials (max 16*256*1024)

// bf16 hi/lo fragment-ordered buffers (uint4 = 4 regs x 2 bf16 = 8 elements)
__device__ uint4 g_w1hi[1605632], g_w1lo[1605632];   // off_w1 1024x12544
__device__ uint4 g_w2hi[131072],  g_w2lo[131072];    // off_w2 1024x1024
__device__ uint4 g_q1hi[802816],  g_q1lo[802816];    // fc1_w  512x12544
__device__ uint4 g_q2hi[32768],   g_q2lo[32768];     // fc2_w  512x512
__device__ uint4 g_ahi[401408],   g_alo[401408];     // activations (256x12544 / 8)

// ---------------------------------------------------------------------------
// Transpose x (B,C,H,W) -> xt (B,H*W,C)
// ---------------------------------------------------------------------------
__global__ void transpose_kernel(const float* __restrict__ x, float* __restrict__ xt) {
    __shared__ float tile[32][33];
    int b  = blockIdx.z;
    int s0 = blockIdx.x * 32;
    int c0 = blockIdx.y * 32;
    int tx = threadIdx.x, ty = threadIdx.y;
    const int HW = H_*W_;
    #pragma unroll
    for (int i = ty; i < 32; i += 8) {
        int c = c0 + i, s = s0 + tx;
        if (c < C_ && s < HW) tile[i][tx] = x[(b*C_ + c)*HW + s];
    }
    __syncthreads();
    #pragma unroll
    for (int i = ty; i < 32; i += 8) {
        int s = s0 + i, c = c0 + tx;
        if (s < HW && c < C_) xt[(b*HW + s)*C_ + c] = tile[tx][i];
    }
}

// ---------------------------------------------------------------------------
// fp32 -> bf16 hi/lo pack
// ---------------------------------------------------------------------------
__device__ __forceinline__ void packpair(float e, float o, uint32_t& h, uint32_t& l) {
    asm("cvt.rn.bf16x2.f32 %0, %1, %2;" : "=r"(h) : "f"(o), "f"(e));
    float re = e - __uint_as_float(h << 16);
    float ro = o - __uint_as_float(h & 0xffff0000u);
    asm("cvt.rn.bf16x2.f32 %0, %1, %2;" : "=r"(l) : "f"(ro), "f"(re));
}

// Weight frag pack (B operand).  uint4 id = ((mb*KT+kt)*8+wt)*32+lane
__device__ __forceinline__ void frag_w_pack(const float* __restrict__ Wm,
                                            uint4* __restrict__ hi,
                                            uint4* __restrict__ lo,
                                            int K, int tid) {
    int lane = tid & 31;
    int rest = tid >> 5;
    int wt = rest & 7; rest >>= 3;
    int KT = K >> 4;
    int kt = rest % KT;
    int mb = rest / KT;
    int m0 = mb*128 + wt*16 + (lane >> 2);
    int k0 = kt*16 + (lane & 3)*2;
    uint4 h, l;
    const float* p00 = Wm + (size_t)m0*K + k0;
    const float* p10 = Wm + (size_t)(m0+8)*K + k0;
    packpair(p00[0], p00[1], h.x, l.x);
    packpair(p00[8], p00[9], h.y, l.y);
    packpair(p10[0], p10[1], h.z, l.z);
    packpair(p10[8], p10[9], h.w, l.w);
    hi[tid] = h; lo[tid] = l;
}

// ---------------------------------------------------------------------------
// Deformable ROI pool body (factorized). off may be nullptr.
// ---------------------------------------------------------------------------
__device__ void pool_body(const float* __restrict__ xt,
                          const float* __restrict__ rois,
                          const float* __restrict__ off,
                          float* __restrict__ out, int n, int ph) {
    int t = threadIdx.x;
    const float* r = rois + n*5;
    int   b  = (int)r[0];
    float sw = rintf(r[1])*SS_ - 0.5f;
    float sh = rintf(r[2])*SS_ - 0.5f;
    float rw = fmaxf((rintf(r[3]) + 1.0f)*SS_ - 0.5f - sw, 0.1f);
    float rh = fmaxf((rintf(r[4]) + 1.0f)*SS_ - 0.5f - sh, 0.1f);
    float bw = rw / (float)OUT_;
    float bh = rh / (float)OUT_;

    __shared__ float s_wx[8], s_wy[8];
    __shared__ int   s_xa, s_ya, s_nx, s_ny, s_cx, s_cy;

    const int base_b = b * (H_*W_) * C_;

    for (int pw = 0; pw < OUT_; pw++) {
        int bin = ph*OUT_ + pw;
        if (t == 0) {
            float txo = off ? off[n*(2*NBIN) + bin] * TRANS_STD_ : 0.0f;
            float wstart = pw*bw + sw + txo*rw;
            int xa = 1000, xb = -1000, cx = 0;
            #pragma unroll
            for (int j = 0; j < 4; j++) {
                float sx = wstart + (float)j * (bw*0.25f);
                if (sx >= -0.5f && sx <= (float)W_ - 0.5f) {
                    cx++;
                    float xc = fminf(fmaxf(sx, 0.0f), (float)(W_-1));
                    int xi0 = (int)floorf(xc);
                    int xi1 = (int)ceilf(xc);
                    xa = min(xa, xi0); xb = max(xb, xi1);
                }
            }
            int nx = (cx > 0) ? (xb - xa + 1) : 0;
            if (nx > 8) nx = 8;
            float wl[8];
            #pragma unroll
            for (int q = 0; q < 8; q++) wl[q] = 0.0f;
            #pragma unroll
            for (int j = 0; j < 4; j++) {
                float sx = wstart + (float)j * (bw*0.25f);
                if (sx >= -0.5f && sx <= (float)W_ - 0.5f) {
                    float xc = fminf(fmaxf(sx, 0.0f), (float)(W_-1));
                    float x0 = floorf(xc);
                    float dx = xc - x0;
                    int xi0 = (int)x0;
                    int xi1 = (int)ceilf(xc);
                    wl[xi0 - xa] += 1.0f - dx;
                    if (xi1 - xa < 8) wl[xi1 - xa] += dx;
                }
            }
            s_xa = xa; s_nx = nx; s_cx = cx;
            #pragma unroll
            for (int q = 0; q < 8; q++) s_wx[q] = wl[q];
        }
        if (t == 32) {
            float tyo = off ? off[n*(2*NBIN) + NBIN + bin] * TRANS_STD_ : 0.0f;
            float hstart = ph*bh + sh + tyo*rh;
            int ya = 1000, yb = -1000, cy = 0;
            #pragma unroll
            for (int i = 0; i < 4; i++) {
                float sy = hstart + (float)i * (bh*0.25f);
                if (sy >= -0.5f && sy <= (float)H_ - 0.5f) {
                    cy++;
                    float yc = fminf(fmaxf(sy, 0.0f), (float)(H_-1));
                    int yi0 = (int)floorf(yc);
                    int yi1 = (int)ceilf(yc);
                    ya = min(ya, yi0); yb = max(yb, yi1);
                }
            }
            int ny = (cy > 0) ? (yb - ya + 1) : 0;
            if (ny > 8) ny = 8;
            float wl[8];
            #pragma unroll
            for (int q = 0; q < 8; q++) wl[q] = 0.0f;
            #pragma unroll
            for (int i = 0; i < 4; i++) {
                float sy = hstart + (float)i * (bh*0.25f);
                if (sy >= -0.5f && sy <= (float)H_ - 0.5f) {
                    float yc = fminf(fmaxf(sy, 0.0f), (float)(H_-1));
                    float y0 = floorf(yc);
                    float dy = yc - y0;
                    int yi0 = (int)y0;
                    int yi1 = (int)ceilf(yc);
                    wl[yi0 - ya] += 1.0f - dy;
                    if (yi1 - ya < 8) wl[yi1 - ya] += dy;
                }
            }
            s_ya = ya; s_ny = ny; s_cy = cy;
            #pragma unroll
            for (int q = 0; q < 8; q++) s_wy[q] = wl[q];
        }
        __syncthreads();

        float inv = 1.0f / fmaxf((float)(s_cx * s_cy), 1.0f);
        float acc = 0.0f;
        int ny = s_ny, nx = s_nx, ya = s_ya, xa = s_xa;
        for (int iy = 0; iy < ny; iy++) {
            float wy = s_wy[iy];
            if (wy == 0.0f) continue;
            int rowoff = base_b + ((ya + iy)*W_ + xa)*C_ + t;
            for (int ix = 0; ix < nx; ix++) {
                float wv = wy * s_wx[ix];
                if (wv != 0.0f) acc += wv * xt[rowoff + ix*C_];
            }
        }
        out[n*IN_ + t*NBIN + bin] = acc * inv;
        __syncthreads();
    }
}

// pool0 (zero offsets) + off_w1 conversion carriers.
// blocks [0,1792): pool (n=bid/7, ph=bid%7); [1792,1832): 40 carriers over 6272 units.
__global__ void pool0_w1_kernel(const float* __restrict__ xt,
                                const float* __restrict__ rois,
                                float* __restrict__ out,
                                const float* __restrict__ w1,
                                uint4* __restrict__ w1h, uint4* __restrict__ w1l) {
    int bid = blockIdx.x;
    if (bid >= 1792) {
        int c = bid - 1792;
        for (int u = c; u < 6272; u += 40)
            frag_w_pack(w1, w1h, w1l, IN_, u*256 + (int)threadIdx.x);
        return;
    }
    pool_body(xt, rois, nullptr, out, bid/7, bid%7);
}

// pool1 (learned offsets), plain
__global__ void pool_kernel(const float* __restrict__ xt,
                            const float* __restrict__ rois,
                            const float* __restrict__ off,
                            float* __restrict__ out) {
    pool_body(xt, rois, off, out, blockIdx.x, blockIdx.y);
}

// ---------------------------------------------------------------------------
// Activation -> fragment-ordered bf16 hi/lo (from fp32 array)
// ---------------------------------------------------------------------------
__global__ void conv_frag_a(const float* __restrict__ A, uint4* __restrict__ hi,
                            uint4* __restrict__ lo, int K, int total) {
    int tid = blockIdx.x * 256 + threadIdx.x;
    if (tid >= total) return;
    int lane = tid & 31;
    int rest = tid >> 5;
    int at = rest & 7; rest >>= 3;
    int KT = K >> 4;
    int kt = rest % KT;
    int nb = rest / KT;
    int m0 = nb*128 + at*16 + (lane >> 2);
    int k0 = kt*16 + (lane & 3)*2;
    uint4 h, l;
    const float* p00 = A + (size_t)m0*K + k0;
    const float* p10 = A + (size_t)(m0+8)*K + k0;
    packpair(p00[0], p00[1], h.x, l.x);
    packpair(p10[0], p10[1], h.y, l.y);
    packpair(p00[8], p00[9], h.z, l.z);
    packpair(p10[8], p10[9], h.w, l.w);
    hi[tid] = h; lo[tid] = l;
}

// ---------------------------------------------------------------------------
// Fused: split-K reduce + bias + ReLU + fragment pack
// ---------------------------------------------------------------------------
__global__ void reduce_frag(const float* __restrict__ part,
                            const float* __restrict__ bias,
                            uint4* __restrict__ hi, uint4* __restrict__ lo,
                            int M, int S) {
    int tid = blockIdx.x * 256 + threadIdx.x;
    int lane = tid & 31;
    int rest = tid >> 5;
    int at = rest & 7; rest >>= 3;
    int KT = M >> 4;
    int kt = rest % KT;
    int nb = rest / KT;
    int m0 = nb*128 + at*16 + (lane >> 2);
    int k0 = kt*16 + (lane & 3)*2;

    float2 bb0 = *(const float2*)(bias + k0);
    float2 bb8 = *(const float2*)(bias + k0 + 8);
    float a00 = bb0.x, a01 = bb0.y, a08 = bb8.x, a09 = bb8.y;
    float b00 = bb0.x, b01 = bb0.y, b08 = bb8.x, b09 = bb8.y;

    const float* p0 = part + (size_t)m0*M + k0;
    const float* p1 = part + (size_t)(m0+8)*M + k0;
    size_t stride = (size_t)N_ * M;
    for (int s = 0; s < S; s++) {
        float2 v;
        v = *(const float2*)(p0 + s*stride);     a00 += v.x; a01 += v.y;
        v = *(const float2*)(p0 + s*stride + 8); a08 += v.x; a09 += v.y;
        v = *(const float2*)(p1 + s*stride);     b00 += v.x; b01 += v.y;
        v = *(const float2*)(p1 + s*stride + 8); b08 += v.x; b09 += v.y;
    }
    a00 = fmaxf(a00, 0.0f); a01 = fmaxf(a01, 0.0f);
    a08 = fmaxf(a08, 0.0f); a09 = fmaxf(a09, 0.0f);
    b00 = fmaxf(b00, 0.0f); b01 = fmaxf(b01, 0.0f);
    b08 = fmaxf(b08, 0.0f); b09 = fmaxf(b09, 0.0f);

    uint4 h, l;
    packpair(a00, a01, h.x, l.x);
    packpair(b00, b01, h.y, l.y);
    packpair(a08, a09, h.z, l.z);
    packpair(b08, b09, h.w, l.w);
    hi[tid] = h; lo[tid] = l;
}

// ---------------------------------------------------------------------------
// bf16 3-term mma.sync GEMM body, split-K, cp.async double-buffered.
// ---------------------------------------------------------------------------
__device__ __forceinline__ void mma_bf16(float* c, const uint4& a,
                                         uint32_t b0, uint32_t b1) {
    asm volatile(
        "mma.sync.aligned.m16n8k16.row.col.f32.bf16.bf16.f32 "
        "{%0,%1,%2,%3}, {%4,%5,%6,%7}, {%8,%9}, {%0,%1,%2,%3};"
        : "+f"(c[0]), "+f"(c[1]), "+f"(c[2]), "+f"(c[3])
        : "r"(a.x), "r"(a.y), "r"(a.z), "r"(a.w), "r"(b0), "r"(b1));
}

__device__ __forceinline__ void cp16(void* smem, const void* g) {
    uint32_t s = (uint32_t)__cvta_generic_to_shared(smem);
    asm volatile("cp.async.cg.shared.global [%0], [%1], 16;" :: "r"(s), "l"(g));
}
__device__ __forceinline__ void cp_commit() {
    asm volatile("cp.async.commit_group;" ::: "memory");
}
__device__ __forceinline__ void cp_wait1() {
    asm volatile("cp.async.wait_group 1;" ::: "memory");
}
__device__ __forceinline__ void cp_wait0() {
    asm volatile("cp.async.wait_group 0;" ::: "memory");
}

__device__ void gemm_body(
    const uint4* __restrict__ Ahi, const uint4* __restrict__ Alo,
    const uint4* __restrict__ Whi, const uint4* __restrict__ Wlo,
    float* __restrict__ part, int M, int KT, int Kc16,
    int mb, int nb, int s) {
    __shared__ uint4 sAh[2][256], sAl[2][256], sWh[2][256], sWl[2][256];

    int tid = threadIdx.x, wid = tid >> 5, lane = tid & 31;
    int wr = wid >> 1, wc = wid & 1;

    float acc[2][8][4];
    #pragma unroll
    for (int i = 0; i < 2; i++)
        #pragma unroll
        for (int j = 0; j < 8; j++)
            #pragma unroll
            for (int q = 0; q < 4; q++) acc[i][j][q] = 0.0f;

    int kt0 = s * Kc16;
    int at0 = wr*2;

    {
        size_t a_off = ((size_t)(nb*KT + kt0)*8)*32 + tid;
        size_t w_off = ((size_t)(mb*KT + kt0)*8)*32 + tid;
        cp16(&sAh[0][tid], Ahi + a_off);
        cp16(&sAl[0][tid], Alo + a_off);
        cp16(&sWh[0][tid], Whi + w_off);
        cp16(&sWl[0][tid], Wlo + w_off);
        cp_commit();
    }

    for (int t = 0; t < Kc16; t++) {
        int buf = t & 1;
        if (t + 1 < Kc16) {
            int kt = kt0 + t + 1;
            int nbuf = (t + 1) & 1;
            size_t a_off = ((size_t)(nb*KT + kt)*8)*32 + tid;
            size_t w_off = ((size_t)(mb*KT + kt)*8)*32 + tid;
            cp16(&sAh[nbuf][tid], Ahi + a_off);
            cp16(&sAl[nbuf][tid], Alo + a_off);
            cp16(&sWh[nbuf][tid], Whi + w_off);
            cp16(&sWl[nbuf][tid], Wlo + w_off);
            cp_commit();
            cp_wait1();
        } else {
            cp_wait0();
        }
        __syncthreads();

        uint4 ah0 = sAh[buf][at0*32 + lane];
        uint4 ah1 = sAh[buf][at0*32 + 32 + lane];
        uint4 al0 = sAl[buf][at0*32 + lane];
        uint4 al1 = sAl[buf][at0*32 + 32 + lane];
        #pragma unroll
        for (int wt = 0; wt < 4; wt++) {
            uint4 wh = sWh[buf][wc*128 + wt*32 + lane];
            uint4 wl = sWl[buf][wc*128 + wt*32 + lane];
            int nf = wt*2;
            mma_bf16(acc[0][nf],   ah0, wh.x, wh.y);
            mma_bf16(acc[0][nf+1], ah0, wh.z, wh.w);
            mma_bf16(acc[1][nf],   ah1, wh.x, wh.y);
            mma_bf16(acc[1][nf+1], ah1, wh.z, wh.w);
            mma_bf16(acc[0][nf],   ah0, wl.x, wl.y);
            mma_bf16(acc[0][nf+1], ah0, wl.z, wl.w);
            mma_bf16(acc[1][nf],   ah1, wl.x, wl.y);
            mma_bf16(acc[1][nf+1], ah1, wl.z, wl.w);
            mma_bf16(acc[0][nf],   al0, wh.x, wh.y);
            mma_bf16(acc[0][nf+1], al0, wh.z, wh.w);
            mma_bf16(acc[1][nf],   al1, wh.x, wh.y);
            mma_bf16(acc[1][nf+1], al1, wh.z, wh.w);
        }
        __syncthreads();
    }

    float* p = part + (size_t)s * N_ * M;
    #pragma unroll
    for (int i = 0; i < 2; i++) {
        int row = nb*128 + wr*32 + i*16 + (lane >> 2);
        #pragma unroll
        for (int nf = 0; nf < 8; nf++) {
            int col = mb*128 + wc*64 + nf*8 + (lane & 3)*2;
            *(float2*)(p + (size_t)row*M + col)     = make_float2(acc[i][nf][0], acc[i][nf][1]);
            *(float2*)(p + (size_t)(row+8)*M + col) = make_float2(acc[i][nf][2], acc[i][nf][3]);
        }
    }
}

// Plain 3D-grid GEMM (gemm2, fc1, fc2)
__global__ __launch_bounds__(256, 2) void gemm_bf16(
    const uint4* __restrict__ Ahi, const uint4* __restrict__ Alo,
    const uint4* __restrict__ Whi, const uint4* __restrict__ Wlo,
    float* __restrict__ part, int M, int KT, int Kc16) {
    gemm_body(Ahi, Alo, Whi, Wlo, part, M, KT, Kc16,
              blockIdx.x, blockIdx.y, blockIdx.z);
}

// gemm1 + carriers converting w2/q1/q2 (not read until gemm2/fc1/fc2).
// blocks [0,256): gemm (mb=bid&7, nb=(bid>>3)&1, s=bid>>4); [256,296): carriers.
__global__ __launch_bounds__(256, 2) void gemm1_fused(
    const uint4* __restrict__ Ahi, const uint4* __restrict__ Alo,
    const uint4* __restrict__ Whi, const uint4* __restrict__ Wlo,
    float* __restrict__ part,
    const float* __restrict__ w2, const float* __restrict__ q1,
    const float* __restrict__ q2,
    uint4* __restrict__ w2h, uint4* __restrict__ w2l,
    uint4* __restrict__ q1h, uint4* __restrict__ q1l,
    uint4* __restrict__ q2h, uint4* __restrict__ q2l) {
    int bid = blockIdx.x;
    if (bid >= 256) {
        int c = bid - 256;
        int t = threadIdx.x;
        for (int u = c; u < 3776; u += 40) {
            if (u < 512)       frag_w_pack(w2, w2h, w2l, DFC_, u*256 + t);
            else if (u < 3648) frag_w_pack(q1, q1h, q1l, IN_,  (u-512)*256 + t);
            else               frag_w_pack(q2, q2h, q2l, FCC_, (u-3648)*256 + t);
        }
        return;
    }
    gemm_body(Ahi, Alo, Whi, Wlo, part, DFC_, 784, 49,
              bid & 7, (bid >> 3) & 1, bid >> 4);
}

// ---------------------------------------------------------------------------
// Reduce split-K partials + bias (+ optional relu), float4 (fp32 output path)
// ---------------------------------------------------------------------------
__global__ void reduce_kernel(const float4* __restrict__ part,
                              const float* __restrict__ bias,
                              float4* __restrict__ C, int M4, int S, int relu) {
    int idx = blockIdx.x * 256 + threadIdx.x;
    int col4 = idx % M4;
    const float4* bp = (const float4*)bias;
    float4 acc = bp[col4];
    for (int s = 0; s < S; s++) {
        float4 v = part[(size_t)s*N_*M4 + idx];
        acc.x += v.x; acc.y += v.y; acc.z += v.z; acc.w += v.w;
    }
    if (relu) {
        acc.x = fmaxf(acc.x, 0.0f); acc.y = fmaxf(acc.y, 0.0f);
        acc.z = fmaxf(acc.z, 0.0f); acc.w = fmaxf(acc.w, 0.0f);
    }
    C[idx] = acc;
}

// ---------------------------------------------------------------------------
// off3 head
// ---------------------------------------------------------------------------
__global__ void off3_kernel(const float* __restrict__ h,
                            const float* __restrict__ w3,
                            const float* __restrict__ b3,
                            float* __restrict__ out) {
    int n = blockIdx.x;
    int tid = threadIdx.x;
    __shared__ float sh[DFC_];
    ((float4*)sh)[tid] = ((const float4*)(h + n*DFC_))[tid];
    __syncthreads();
    int warp = tid >> 5, lane = tid & 31;
    for (int o = warp; o < 2*NBIN; o += 8) {
        const float4* w = (const float4*)(w3 + o*DFC_);
        float acc = 0.0f;
        #pragma unroll
        for (int i = lane; i < DFC_/4; i += 32) {
            float4 wv = w[i];
            float4 av = ((const float4*)sh)[i];
            acc += wv.x*av.x + wv.y*av.y + wv.z*av.z + wv.w*av.w;
        }
        #pragma unroll
        for (int d = 16; d > 0; d >>= 1) acc += __shfl_down_sync(0xffffffffu, acc, d);
        if (lane == 0) out[n*(2*NBIN) + o] = acc + b3[o];
    }
}

// ---------------------------------------------------------------------------
// box head
// ---------------------------------------------------------------------------
__global__ void box_kernel(const float* __restrict__ f2,
                           const float* __restrict__ bw,
                           const float* __restrict__ bb,
                           float* __restrict__ out) {
    int n = blockIdx.x;
    int w = threadIdx.x >> 5;
    int lane = threadIdx.x & 31;
    float acc = 0.0f;
    for (int k = lane; k < FCC_; k += 32) acc += f2[n*FCC_ + k]*bw[w*FCC_ + k];
    #pragma unroll
    for (int o = 16; o > 0; o >>= 1) acc += __shfl_down_sync(0xffffffffu, acc, o);
    if (lane == 0) out[n*4 + w] = acc + bb[w];
}

// ---------------------------------------------------------------------------
extern "C" void kernel_launch(void* const* d_in, const int* in_sizes, int n_in,
                              void* d_out, int out_size) {
    const float* x      = (const float*)d_in[0];
    const float* rois   = (const float*)d_in[1];
    const float* off_w1 = (const float*)d_in[2];
    const float* off_b1 = (const float*)d_in[3];
    const float* off_w2 = (const float*)d_in[4];
    const float* off_b2 = (const float*)d_in[5];
    const float* off_w3 = (const float*)d_in[6];
    const float* off_b3 = (const float*)d_in[7];
    const float* fc1_w  = (const float*)d_in[8];
    const float* fc1_b  = (const float*)d_in[9];
    const float* fc2_w  = (const float*)d_in[10];
    const float* fc2_b  = (const float*)d_in[11];
    const float* box_w  = (const float*)d_in[12];
    const float* box_b  = (const float*)d_in[13];
    float* out = (float*)d_out;

    float *xt, *p0, *h2, *offb, *p1, *f2, *part;
    uint4 *w1hi, *w1lo, *w2hi, *w2lo, *q1hi, *q1lo, *q2hi, *q2lo, *ahi, *alo;
    cudaGetSymbolAddress((void**)&xt,   g_xt);
    cudaGetSymbolAddress((void**)&p0,   g_p0);
    cudaGetSymbolAddress((void**)&h2,   g_h2);
    cudaGetSymbolAddress((void**)&offb, g_off);
    cudaGetSymbolAddress((void**)&p1,   g_p1);
    cudaGetSymbolAddress((void**)&f2,   g_f2);
    cudaGetSymbolAddress((void**)&part, g_part);
    cudaGetSymbolAddress((void**)&w1hi, g_w1hi);
    cudaGetSymbolAddress((void**)&w1lo, g_w1lo);
    cudaGetSymbolAddress((void**)&w2hi, g_w2hi);
    cudaGetSymbolAddress((void**)&w2lo, g_w2lo);
    cudaGetSymbolAddress((void**)&q1hi, g_q1hi);
    cudaGetSymbolAddress((void**)&q1lo, g_q1lo);
    cudaGetSymbolAddress((void**)&q2hi, g_q2hi);
    cudaGetSymbolAddress((void**)&q2lo, g_q2lo);
    cudaGetSymbolAddress((void**)&ahi,  g_ahi);
    cudaGetSymbolAddress((void**)&alo,  g_alo);

    // 1. x -> xt
    {
        dim3 grid((H_*W_ + 31)/32, (C_ + 31)/32, B_);
        dim3 block(32, 8);
        transpose_kernel<<<grid, block>>>(x, xt);
    }
    // 2. pool0 (zero offsets) + w1 conversion carriers
    pool0_w1_kernel<<<1832, 256>>>(xt, rois, p0, off_w1, w1hi, w1lo);
    conv_frag_a<<<1568, 256>>>(p0, ahi, alo, IN_, 401408);

    // 3. h1 frags = relu(p0 @ off_w1^T + b1)  [256x1024, K=12544], S=16 (Kc16=49)
    //    + carriers converting w2/q1/q2 under the gemm.
    gemm1_fused<<<296, 256>>>(ahi, alo, w1hi, w1lo, part,
                              off_w2, fc1_w, fc2_w,
                              w2hi, w2lo, q1hi, q1lo, q2hi, q2lo);
    reduce_frag<<<128, 256>>>(part, off_b1, ahi, alo, DFC_, 16);

    // 4. h2 = relu(h1 @ off_w2^T + b2)  [256x1024, K=1024], S=16 (Kc16=4)
    gemm_bf16<<<dim3(8, 2, 16), 256>>>(ahi, alo, w2hi, w2lo, part, DFC_, 64, 4);
    reduce_kernel<<<(N_*DFC_/4)/256, 256>>>((const float4*)part, off_b2, (float4*)h2, DFC_/4, 16, 1);

    // 5. off = h2 @ off_w3^T + b3       [256x98]
    off3_kernel<<<N_, 256>>>(h2, off_w3, off_b3, offb);

    // 6. pool1 (learned offsets) -> p1, convert
    pool_kernel<<<dim3(N_, OUT_), 256>>>(xt, rois, offb, p1);
    conv_frag_a<<<1568, 256>>>(p1, ahi, alo, IN_, 401408);

    // 7. f1 frags = relu(p1 @ fc1_w^T + b)  [256x512, K=12544], S=28 (Kc16=28)
    gemm_bf16<<<dim3(4, 2, 28), 256>>>(ahi, alo, q1hi, q1lo, part, FCC_, 784, 28);
    reduce_frag<<<64, 256>>>(part, fc1_b, ahi, alo, FCC_, 28);

    // 8. f2 = relu(f1 @ fc2_w^T + b)    [256x512, K=512], S=16 (Kc16=2)
    gemm_bf16<<<dim3(4, 2, 16), 256>>>(ahi, alo, q2hi, q2lo, part, FCC_, 32, 2);
    reduce_kernel<<<(N_*FCC_/4)/256, 256>>>((const float4*)part, fc2_b, (float4*)f2, FCC_/4, 16, 1);

    // 9. out = f2 @ box_w^T + box_b     [256x4]
    box_kernel<<<N_, 128>>>(f2, box_w, box_b, out);
}